// round 3
// baseline (speedup 1.0000x reference)
#include <cuda_runtime.h>
#include <math.h>

#define N 4096
#define NN (4096ULL*4096ULL)

// ---------------- scratch (device globals; no runtime allocation) ----------------
__device__ float2 g_bufA[NN];        // 128 MB: after row FFT (pass 1)
__device__ float2 g_bufB[NN];        // 128 MB: transposed
__device__ float  g_img[NN];         // 64 MB: real spatial image (TRANSPOSED orientation)
__device__ float  g_c1[1365*1365];
__device__ float  g_c2[455*455];
__device__ float  g_c3[151*151];
__device__ float2 g_tw[1024];        // W[k] = exp(+2*pi*i*k/4096)

// ---------------- complex helpers ----------------
__device__ __forceinline__ float2 cmul(float2 a, float2 b) {
    return make_float2(fmaf(a.x, b.x, -a.y * b.y), fmaf(a.x, b.y, a.y * b.x));
}
__device__ __forceinline__ float2 cadd(float2 a, float2 b) { return make_float2(a.x + b.x, a.y + b.y); }
__device__ __forceinline__ float2 csub(float2 a, float2 b) { return make_float2(a.x - b.x, a.y - b.y); }
// i * z
__device__ __forceinline__ float2 cmuli(float2 z) { return make_float2(-z.y, z.x); }

// Bank-conflict-killing smem index swizzle: permutes within each 128B line,
// injects bits 4-7 into bank bits. All FFT smem accesses go through this.
__device__ __forceinline__ int SW(int i) { return i ^ ((i >> 4) & 15); }

// ---------------- twiddle init ----------------
__global__ void twiddle_init() {
    int k = threadIdx.x;  // 1024 threads
    double ang = 6.283185307179586476925286766559 * (double)k / 4096.0;
    g_tw[k] = make_float2((float)cos(ang), (float)sin(ang));
}

// ---------------- Stockham radix-8 inverse FFT stage (compile-time S) ----------------
// Inverse convention: X[k] = sum_j x[j] * exp(+2*pi*i*j*k/N)  (unnormalized).
// out[q + 8*ps + m*S] = W^(m*ps) * sum_k in[t + 512k] * w8^(mk),  t = ps + q.
template<int S>
__device__ __forceinline__ void stage8(const float2* __restrict__ in,
                                       float2* __restrict__ out, int t)
{
    const float R8 = 0.70710678118654752f;
    const int q  = t & (S - 1);
    const int ps = t - q;

    float2 x0 = in[SW(t)];
    float2 x1 = in[SW(t + 512)];
    float2 x2 = in[SW(t + 1024)];
    float2 x3 = in[SW(t + 1536)];
    float2 x4 = in[SW(t + 2048)];
    float2 x5 = in[SW(t + 2560)];
    float2 x6 = in[SW(t + 3072)];
    float2 x7 = in[SW(t + 3584)];

    // E = inverse DFT4 of (x0,x2,x4,x6); O = inverse DFT4 of (x1,x3,x5,x7)
    float2 apc = cadd(x0, x4), amc = csub(x0, x4);
    float2 bpd = cadd(x2, x6), bmd = csub(x2, x6);
    float2 E0 = cadd(apc, bpd);
    float2 E1 = cadd(amc, cmuli(bmd));
    float2 E2 = csub(apc, bpd);
    float2 E3 = csub(amc, cmuli(bmd));

    float2 opc = cadd(x1, x5), omc = csub(x1, x5);
    float2 ppd = cadd(x3, x7), pmd = csub(x3, x7);
    float2 O0 = cadd(opc, ppd);
    float2 O1 = cadd(omc, cmuli(pmd));
    float2 O2 = csub(opc, ppd);
    float2 O3 = csub(omc, cmuli(pmd));

    // combine with w8^m:  w8^1=(R8,R8), w8^2=i, w8^3=(-R8,R8)
    float2 T1 = cmul(make_float2( R8, R8), O1);
    float2 T2 = cmuli(O2);
    float2 T3 = cmul(make_float2(-R8, R8), O3);

    float2 y0 = cadd(E0, O0), y4 = csub(E0, O0);
    float2 y1 = cadd(E1, T1), y5 = csub(E1, T1);
    float2 y2 = cadd(E2, T2), y6 = csub(E2, T2);
    float2 y3 = cadd(E3, T3), y7 = csub(E3, T3);

    if (S != 512) {  // S==512 -> ps==0 -> all twiddles are 1
        float2 w1 = g_tw[ps];
        float2 w2 = cmul(w1, w1);
        float2 w3 = cmul(w2, w1);
        float2 w4 = cmul(w2, w2);
        float2 w5 = cmul(w3, w2);
        float2 w6 = cmul(w3, w3);
        float2 w7 = cmul(w4, w3);
        y1 = cmul(w1, y1); y2 = cmul(w2, y2); y3 = cmul(w3, y3);
        y4 = cmul(w4, y4); y5 = cmul(w5, y5); y6 = cmul(w6, y6);
        y7 = cmul(w7, y7);
    }

    const int ob = q + 8 * ps;
    out[SW(ob)]         = y0;
    out[SW(ob + S)]     = y1;
    out[SW(ob + 2 * S)] = y2;
    out[SW(ob + 3 * S)] = y3;
    out[SW(ob + 4 * S)] = y4;
    out[SW(ob + 5 * S)] = y5;
    out[SW(ob + 6 * S)] = y6;
    out[SW(ob + 7 * S)] = y7;
}

__device__ __forceinline__ void fft4096_r8(float2* s0, float2* s1, int t)
{
    stage8<1>(s0, s1, t);   __syncthreads();
    stage8<8>(s1, s0, t);   __syncthreads();
    stage8<64>(s0, s1, t);  __syncthreads();
    stage8<512>(s1, s0, t); __syncthreads();
}

// ---------------- pass 1: elementwise (mag/phase) fused + row IFFT along axis -1 ----------------
__global__ void __launch_bounds__(512, 2)
fft_pass1(const float* __restrict__ xr, const float* __restrict__ xi,
          const float* __restrict__ mk, const float* __restrict__ pk)
{
    extern __shared__ float2 sm[];
    float2* s0 = sm;
    float2* s1 = sm + 4096;
    const int row = blockIdx.x;
    const int t   = threadIdx.x;
    const size_t base = (size_t)row * N;
#pragma unroll
    for (int e = 0; e < 8; e++) {
        int idx = t + e * 512;
        float a = xr[base + idx];
        float b = xi[base + idx];
        float m = sqrtf(fmaf(a, a, b * b)) * mk[base + idx];
        float p = atan2f(b, a) * pk[base + idx];
        float sp, cp;
        sincosf(p, &sp, &cp);
        s0[SW(idx)] = make_float2(m * cp, m * sp);
    }
    __syncthreads();
    fft4096_r8(s0, s1, t);
#pragma unroll
    for (int e = 0; e < 8; e++) {
        int idx = t + e * 512;
        g_bufA[base + idx] = s0[SW(idx)];
    }
}

// ---------------- complex transpose (32x32 tiles) ----------------
__global__ void __launch_bounds__(256)
transpose_c()
{
    __shared__ float2 tile[32][33];
    int x  = blockIdx.x * 32 + threadIdx.x;
    int y0 = blockIdx.y * 32;
#pragma unroll
    for (int j = threadIdx.y; j < 32; j += 8)
        tile[j][threadIdx.x] = g_bufA[(size_t)(y0 + j) * N + x];
    __syncthreads();
    int x2 = blockIdx.y * 32 + threadIdx.x;
    int y2 = blockIdx.x * 32;
#pragma unroll
    for (int j = threadIdx.y; j < 32; j += 8)
        g_bufB[(size_t)(y2 + j) * N + x2] = tile[threadIdx.x][j];
}

// ---------------- pass 2: IFFT along original axis -2, write real part ----------------
__global__ void __launch_bounds__(512, 2)
fft_pass2()
{
    extern __shared__ float2 sm[];
    float2* s0 = sm;
    float2* s1 = sm + 4096;
    const int row = blockIdx.x;        // n2
    const int t   = threadIdx.x;
    const size_t base = (size_t)row * N;
#pragma unroll
    for (int e = 0; e < 8; e++) {
        int idx = t + e * 512;
        s0[SW(idx)] = g_bufB[base + idx];
    }
    __syncthreads();
    fft4096_r8(s0, s1, t);
    const float scale = 1.0f / 16777216.0f;   // 1/N^2
#pragma unroll
    for (int e = 0; e < 8; e++) {
        int idx = t + e * 512;                // n1
        float sgn = ((row + idx) & 1) ? -scale : scale;
        g_img[base + idx] = s0[SW(idx)].x * sgn;
    }
}

// ---------------- conv 3x3 stride 3 + bias + BN + PReLU (on TRANSPOSED image) ----------------
__device__ __forceinline__ float conv_point(const float* __restrict__ in, int Win,
                                            int i, int j, const float* w,
                                            float cb, float sc, float sh, float al)
{
    const float* r0 = in + (size_t)(3 * i) * Win + 3 * j;
    float acc = 0.0f;
#pragma unroll
    for (int dy = 0; dy < 3; dy++)
#pragma unroll
        for (int dx = 0; dx < 3; dx++)
            acc = fmaf(r0[(size_t)dy * Win + dx], w[dy * 3 + dx], acc);
    acc += cb;
    acc = fmaf(acc, sc, sh);
    return (acc >= 0.0f) ? acc : al * acc;
}

__global__ void __launch_bounds__(256)
conv_bn_prelu(const float* __restrict__ in, float* __restrict__ out,
              int Win, int Wout, int Hout,
              const float* __restrict__ cw, const float* __restrict__ cb,
              const float* __restrict__ bg, const float* __restrict__ bb,
              const float* __restrict__ bm, const float* __restrict__ bv,
              const float* __restrict__ pa, int layer)
{
    int j = blockIdx.x * blockDim.x + threadIdx.x;
    int i = blockIdx.y * blockDim.y + threadIdx.y;
    if (i >= Hout || j >= Wout) return;
    const float* wb = cw + layer * 9;
    float w[9];
#pragma unroll
    for (int dy = 0; dy < 3; dy++)
#pragma unroll
        for (int dx = 0; dx < 3; dx++)
            w[dy * 3 + dx] = __ldg(&wb[dx * 3 + dy]);   // transposed weight
    float rs = rsqrtf(__ldg(&bv[layer]) + 1e-5f);
    float gg = __ldg(&bg[layer]);
    float sc = gg * rs;
    float sh = __ldg(&bb[layer]) - gg * __ldg(&bm[layer]) * rs;
    out[(size_t)i * Wout + j] =
        conv_point(in, Win, i, j, w, __ldg(&cb[layer]), sc, sh, __ldg(&pa[layer]));
}

// ---------------- fused tail: conv4 + conv5 + FC5 + LN + PReLU + FC6 (one block) ----------------
__global__ void __launch_bounds__(256, 1)
tail_kernel(const float* __restrict__ c3,
            const float* __restrict__ cw, const float* __restrict__ cbv,
            const float* __restrict__ bg, const float* __restrict__ bb,
            const float* __restrict__ bm, const float* __restrict__ bv,
            const float* __restrict__ pa,
            const float* __restrict__ fc5w, const float* __restrict__ fc5b,
            const float* __restrict__ lng,  const float* __restrict__ lnb,
            const float* __restrict__ p5a,
            const float* __restrict__ fc6w, const float* __restrict__ fc6b,
            float* __restrict__ out)
{
    __shared__ float c4s[2500];
    __shared__ float c5s[256];
    __shared__ float h[82];
    __shared__ float mu_s, rstd_s;
    const int t = threadIdx.x;

    // ---- conv4: g_c3 (151x151) -> c4s (50x50)
    {
        const int layer = 3;
        float w[9];
#pragma unroll
        for (int dy = 0; dy < 3; dy++)
#pragma unroll
            for (int dx = 0; dx < 3; dx++)
                w[dy * 3 + dx] = cw[layer * 9 + dx * 3 + dy];
        float rs = rsqrtf(bv[layer] + 1e-5f);
        float sc = bg[layer] * rs;
        float sh = bb[layer] - bg[layer] * bm[layer] * rs;
        for (int o = t; o < 2500; o += 256) {
            int i = o / 50, j = o % 50;
            c4s[o] = conv_point(c3, 151, i, j, w, cbv[layer], sc, sh, pa[layer]);
        }
    }
    __syncthreads();

    // ---- conv5: c4s (50x50) -> c5s (16x16)
    {
        const int layer = 4;
        float w[9];
#pragma unroll
        for (int dy = 0; dy < 3; dy++)
#pragma unroll
            for (int dx = 0; dx < 3; dx++)
                w[dy * 3 + dx] = cw[layer * 9 + dx * 3 + dy];
        float rs = rsqrtf(bv[layer] + 1e-5f);
        float sc = bg[layer] * rs;
        float sh = bb[layer] - bg[layer] * bm[layer] * rs;
        if (t < 256) {
            int i = t >> 4, j = t & 15;
            c5s[t] = conv_point(c4s, 50, i, j, w, cbv[layer], sc, sh, pa[layer]);
        }
    }
    __syncthreads();

    // ---- FC5 (un-transpose flatten: v=i*16+j reads c5s[j*16+i])
    for (int o = t; o < 82; o += 256) {
        float acc = fc5b[o];
        for (int v = 0; v < 256; v++) {
            int i = v >> 4, j = v & 15;
            acc = fmaf(c5s[j * 16 + i], fc5w[v * 82 + o], acc);
        }
        h[o] = acc;
    }
    __syncthreads();
    if (t == 0) {
        float mu = 0.0f;
        for (int o = 0; o < 82; o++) mu += h[o];
        mu *= (1.0f / 82.0f);
        float var = 0.0f;
        for (int o = 0; o < 82; o++) { float dd = h[o] - mu; var = fmaf(dd, dd, var); }
        var *= (1.0f / 82.0f);
        mu_s = mu;
        rstd_s = rsqrtf(var + 1e-5f);
    }
    __syncthreads();
    if (t < 5) {
        float alpha = p5a[0];
        float acc = fc6b[t];
        for (int k = 0; k < 82; k++) {
            float v = (h[k] - mu_s) * rstd_s * lng[k] + lnb[k];
            v = (v >= 0.0f) ? v : alpha * v;
            acc = fmaf(v, fc6w[k * 5 + t], acc);
        }
        out[t] = acc;
    }
}

// ---------------- launch ----------------
extern "C" void kernel_launch(void* const* d_in, const int* in_sizes, int n_in,
                              void* d_out, int out_size)
{
    const float* xr    = (const float*)d_in[0];
    const float* xi    = (const float*)d_in[1];
    const float* mk    = (const float*)d_in[2];
    const float* pk    = (const float*)d_in[3];
    const float* convw = (const float*)d_in[4];
    const float* convb = (const float*)d_in[5];
    const float* bng   = (const float*)d_in[6];
    const float* bnb   = (const float*)d_in[7];
    const float* bnm   = (const float*)d_in[8];
    const float* bnv   = (const float*)d_in[9];
    const float* pra   = (const float*)d_in[10];
    const float* fc5w  = (const float*)d_in[11];
    const float* fc5b  = (const float*)d_in[12];
    const float* lng   = (const float*)d_in[13];
    const float* lnb   = (const float*)d_in[14];
    const float* p5a   = (const float*)d_in[15];
    const float* fc6w  = (const float*)d_in[16];
    const float* fc6b  = (const float*)d_in[17];
    float* out = (float*)d_out;

    cudaFuncSetAttribute(fft_pass1, cudaFuncAttributeMaxDynamicSharedMemorySize, 65536);
    cudaFuncSetAttribute(fft_pass2, cudaFuncAttributeMaxDynamicSharedMemorySize, 65536);

    float *img, *c1, *c2, *c3;
    cudaGetSymbolAddress((void**)&img, g_img);
    cudaGetSymbolAddress((void**)&c1,  g_c1);
    cudaGetSymbolAddress((void**)&c2,  g_c2);
    cudaGetSymbolAddress((void**)&c3,  g_c3);

    twiddle_init<<<1, 1024>>>();
    fft_pass1<<<4096, 512, 65536>>>(xr, xi, mk, pk);
    transpose_c<<<dim3(128, 128), dim3(32, 8)>>>();
    fft_pass2<<<4096, 512, 65536>>>();

    dim3 cb(32, 8);
    conv_bn_prelu<<<dim3((1365 + 31) / 32, (1365 + 7) / 8), cb>>>(img, c1, 4096, 1365, 1365,
        convw, convb, bng, bnb, bnm, bnv, pra, 0);
    conv_bn_prelu<<<dim3((455 + 31) / 32, (455 + 7) / 8), cb>>>(c1, c2, 1365, 455, 455,
        convw, convb, bng, bnb, bnm, bnv, pra, 1);
    conv_bn_prelu<<<dim3((151 + 31) / 32, (151 + 7) / 8), cb>>>(c2, c3, 455, 151, 151,
        convw, convb, bng, bnb, bnm, bnv, pra, 2);

    tail_kernel<<<1, 256>>>(c3, convw, convb, bng, bnb, bnm, bnv, pra,
                            fc5w, fc5b, lng, lnb, p5a, fc6w, fc6b, out);
}

// round 4
// speedup vs baseline: 1.5526x; 1.5526x over previous
#include <cuda_runtime.h>
#include <math.h>

#define N 4096
#define NN (4096ULL*4096ULL)

// ---------------- scratch (device globals; no runtime allocation) ----------------
__device__ float2 g_bufA[NN];        // 128 MB: after row FFT (pass 1)
__device__ float2 g_bufB[NN];        // 128 MB: transposed
__device__ float  g_img[NN];         // 64 MB: real spatial image (TRANSPOSED orientation)
__device__ float  g_c1[1365*1365];
__device__ float  g_c2[455*455];
__device__ float  g_c3[151*151];
__device__ float2 g_tw[1024];        // W[k] = exp(+2*pi*i*k/4096)

// ---------------- complex helpers ----------------
__device__ __forceinline__ float2 cmul(float2 a, float2 b) {
    return make_float2(fmaf(a.x, b.x, -a.y * b.y), fmaf(a.x, b.y, a.y * b.x));
}
__device__ __forceinline__ float2 cadd(float2 a, float2 b) { return make_float2(a.x + b.x, a.y + b.y); }
__device__ __forceinline__ float2 csub(float2 a, float2 b) { return make_float2(a.x - b.x, a.y - b.y); }
__device__ __forceinline__ float2 cmuli(float2 z) { return make_float2(-z.y, z.x); }

// Bank-conflict-killing smem index swizzle.
__device__ __forceinline__ int SW(int i) { return i ^ ((i >> 4) & 15); }

// ---------------- fast atan2 (11th-order minimax, ~1e-7 abs err) ----------------
__device__ __forceinline__ float fast_atan2f(float y, float x)
{
    float ax = fabsf(x), ay = fabsf(y);
    float mx = fmaxf(ax, ay);
    float mn = fminf(ax, ay);
    float r  = __fdividef(mn, mx);
    float s  = r * r;
    float p  =             -0.0117212f;
    p = fmaf(p, s,  0.05265332f);
    p = fmaf(p, s, -0.11643287f);
    p = fmaf(p, s,  0.19354346f);
    p = fmaf(p, s, -0.33262347f);
    p = fmaf(p, s,  0.99997726f);
    float a = p * r;
    a = (ay > ax) ? (1.5707963267948966f - a) : a;
    a = (x < 0.0f) ? (3.1415926535897932f - a) : a;
    return (y < 0.0f) ? -a : a;
}

// ---------------- twiddle init ----------------
__global__ void twiddle_init() {
    int k = threadIdx.x;  // 1024 threads
    double ang = 6.283185307179586476925286766559 * (double)k / 4096.0;
    g_tw[k] = make_float2((float)cos(ang), (float)sin(ang));
}

// ---------------- Stockham radix-8 inverse FFT stage (compile-time S) ----------------
template<int S>
__device__ __forceinline__ void stage8(const float2* __restrict__ in,
                                       float2* __restrict__ out, int t)
{
    const float R8 = 0.70710678118654752f;
    const int q  = t & (S - 1);
    const int ps = t - q;

    float2 x0 = in[SW(t)];
    float2 x1 = in[SW(t + 512)];
    float2 x2 = in[SW(t + 1024)];
    float2 x3 = in[SW(t + 1536)];
    float2 x4 = in[SW(t + 2048)];
    float2 x5 = in[SW(t + 2560)];
    float2 x6 = in[SW(t + 3072)];
    float2 x7 = in[SW(t + 3584)];

    float2 apc = cadd(x0, x4), amc = csub(x0, x4);
    float2 bpd = cadd(x2, x6), bmd = csub(x2, x6);
    float2 E0 = cadd(apc, bpd);
    float2 E1 = cadd(amc, cmuli(bmd));
    float2 E2 = csub(apc, bpd);
    float2 E3 = csub(amc, cmuli(bmd));

    float2 opc = cadd(x1, x5), omc = csub(x1, x5);
    float2 ppd = cadd(x3, x7), pmd = csub(x3, x7);
    float2 O0 = cadd(opc, ppd);
    float2 O1 = cadd(omc, cmuli(pmd));
    float2 O2 = csub(opc, ppd);
    float2 O3 = csub(omc, cmuli(pmd));

    float2 T1 = cmul(make_float2( R8, R8), O1);
    float2 T2 = cmuli(O2);
    float2 T3 = cmul(make_float2(-R8, R8), O3);

    float2 y0 = cadd(E0, O0), y4 = csub(E0, O0);
    float2 y1 = cadd(E1, T1), y5 = csub(E1, T1);
    float2 y2 = cadd(E2, T2), y6 = csub(E2, T2);
    float2 y3 = cadd(E3, T3), y7 = csub(E3, T3);

    if (S != 512) {  // S==512 -> ps==0 -> all twiddles are 1
        float2 w1 = g_tw[ps];
        float2 w2 = cmul(w1, w1);
        float2 w3 = cmul(w2, w1);
        float2 w4 = cmul(w2, w2);
        float2 w5 = cmul(w3, w2);
        float2 w6 = cmul(w3, w3);
        float2 w7 = cmul(w4, w3);
        y1 = cmul(w1, y1); y2 = cmul(w2, y2); y3 = cmul(w3, y3);
        y4 = cmul(w4, y4); y5 = cmul(w5, y5); y6 = cmul(w6, y6);
        y7 = cmul(w7, y7);
    }

    const int ob = q + 8 * ps;
    out[SW(ob)]         = y0;
    out[SW(ob + S)]     = y1;
    out[SW(ob + 2 * S)] = y2;
    out[SW(ob + 3 * S)] = y3;
    out[SW(ob + 4 * S)] = y4;
    out[SW(ob + 5 * S)] = y5;
    out[SW(ob + 6 * S)] = y6;
    out[SW(ob + 7 * S)] = y7;
}

__device__ __forceinline__ void fft4096_r8(float2* s0, float2* s1, int t)
{
    stage8<1>(s0, s1, t);   __syncthreads();
    stage8<8>(s1, s0, t);   __syncthreads();
    stage8<64>(s0, s1, t);  __syncthreads();
    stage8<512>(s1, s0, t); __syncthreads();
}

// ---------------- pass 1: elementwise (fast math) fused + row IFFT along axis -1 ----------------
__global__ void __launch_bounds__(512, 2)
fft_pass1(const float* __restrict__ xr, const float* __restrict__ xi,
          const float* __restrict__ mk, const float* __restrict__ pk)
{
    extern __shared__ float2 sm[];
    float2* s0 = sm;
    float2* s1 = sm + 4096;
    const int row = blockIdx.x;
    const int t   = threadIdx.x;
    const int base4 = row * (N / 4);
    const float4* xr4 = (const float4*)xr;
    const float4* xi4 = (const float4*)xi;
    const float4* mk4 = (const float4*)mk;
    const float4* pk4 = (const float4*)pk;
#pragma unroll
    for (int e = 0; e < 2; e++) {
        int i4 = t + 512 * e;
        float4 ar = xr4[base4 + i4];
        float4 br = xi4[base4 + i4];
        float4 mr = mk4[base4 + i4];
        float4 pr = pk4[base4 + i4];
        float av[4] = {ar.x, ar.y, ar.z, ar.w};
        float bv[4] = {br.x, br.y, br.z, br.w};
        float mv[4] = {mr.x, mr.y, mr.z, mr.w};
        float pv[4] = {pr.x, pr.y, pr.z, pr.w};
#pragma unroll
        for (int j = 0; j < 4; j++) {
            float a = av[j], b = bv[j];
            float m = sqrtf(fmaf(a, a, b * b)) * mv[j];
            float p = fast_atan2f(b, a) * pv[j];
            float sp, cp;
            __sincosf(p, &sp, &cp);
            s0[SW(4 * i4 + j)] = make_float2(m * cp, m * sp);
        }
    }
    __syncthreads();
    fft4096_r8(s0, s1, t);
    const int base2 = row * (N / 2);
    float4* outA = (float4*)g_bufA;
#pragma unroll
    for (int e = 0; e < 4; e++) {
        int i2 = t + 512 * e;
        float2 a = s0[SW(2 * i2)];
        float2 b = s0[SW(2 * i2 + 1)];
        outA[base2 + i2] = make_float4(a.x, a.y, b.x, b.y);
    }
}

// ---------------- complex transpose (32x32 tiles) ----------------
__global__ void __launch_bounds__(256)
transpose_c()
{
    __shared__ float2 tile[32][33];
    int x  = blockIdx.x * 32 + threadIdx.x;
    int y0 = blockIdx.y * 32;
#pragma unroll
    for (int j = threadIdx.y; j < 32; j += 8)
        tile[j][threadIdx.x] = g_bufA[(size_t)(y0 + j) * N + x];
    __syncthreads();
    int x2 = blockIdx.y * 32 + threadIdx.x;
    int y2 = blockIdx.x * 32;
#pragma unroll
    for (int j = threadIdx.y; j < 32; j += 8)
        g_bufB[(size_t)(y2 + j) * N + x2] = tile[threadIdx.x][j];
}

// ---------------- pass 2: IFFT along original axis -2, write real part ----------------
__global__ void __launch_bounds__(512, 2)
fft_pass2()
{
    extern __shared__ float2 sm[];
    float2* s0 = sm;
    float2* s1 = sm + 4096;
    const int row = blockIdx.x;        // n2
    const int t   = threadIdx.x;
    const int base2 = row * (N / 2);
    const float4* inB = (const float4*)g_bufB;
#pragma unroll
    for (int e = 0; e < 4; e++) {
        int i2 = t + 512 * e;
        float4 v = inB[base2 + i2];
        s0[SW(2 * i2)]     = make_float2(v.x, v.y);
        s0[SW(2 * i2 + 1)] = make_float2(v.z, v.w);
    }
    __syncthreads();
    fft4096_r8(s0, s1, t);
    const float scale = 1.0f / 16777216.0f;   // 1/N^2
    const float sg0 = (row & 1) ? -scale : scale;
    const int base4 = row * (N / 4);
    float4* outI = (float4*)g_img;
#pragma unroll
    for (int e = 0; e < 2; e++) {
        int i4 = t + 512 * e;
        int idx = 4 * i4;
        float v0 = s0[SW(idx)].x     *  sg0;
        float v1 = s0[SW(idx + 1)].x * -sg0;
        float v2 = s0[SW(idx + 2)].x *  sg0;
        float v3 = s0[SW(idx + 3)].x * -sg0;
        outI[base4 + i4] = make_float4(v0, v1, v2, v3);
    }
}

// ---------------- conv 3x3 stride 3 + bias + BN + PReLU (on TRANSPOSED image) ----------------
__device__ __forceinline__ float conv_point(const float* __restrict__ in, int Win,
                                            int i, int j, const float* w,
                                            float cb, float sc, float sh, float al)
{
    const float* r0 = in + (size_t)(3 * i) * Win + 3 * j;
    float acc = 0.0f;
#pragma unroll
    for (int dy = 0; dy < 3; dy++)
#pragma unroll
        for (int dx = 0; dx < 3; dx++)
            acc = fmaf(r0[(size_t)dy * Win + dx], w[dy * 3 + dx], acc);
    acc += cb;
    acc = fmaf(acc, sc, sh);
    return (acc >= 0.0f) ? acc : al * acc;
}

__global__ void __launch_bounds__(256)
conv_bn_prelu(const float* __restrict__ in, float* __restrict__ out,
              int Win, int Wout, int Hout,
              const float* __restrict__ cw, const float* __restrict__ cb,
              const float* __restrict__ bg, const float* __restrict__ bb,
              const float* __restrict__ bm, const float* __restrict__ bv,
              const float* __restrict__ pa, int layer)
{
    int j = blockIdx.x * blockDim.x + threadIdx.x;
    int i = blockIdx.y * blockDim.y + threadIdx.y;
    if (i >= Hout || j >= Wout) return;
    const float* wb = cw + layer * 9;
    float w[9];
#pragma unroll
    for (int dy = 0; dy < 3; dy++)
#pragma unroll
        for (int dx = 0; dx < 3; dx++)
            w[dy * 3 + dx] = __ldg(&wb[dx * 3 + dy]);   // transposed weight
    float rs = rsqrtf(__ldg(&bv[layer]) + 1e-5f);
    float gg = __ldg(&bg[layer]);
    float sc = gg * rs;
    float sh = __ldg(&bb[layer]) - gg * __ldg(&bm[layer]) * rs;
    out[(size_t)i * Wout + j] =
        conv_point(in, Win, i, j, w, __ldg(&cb[layer]), sc, sh, __ldg(&pa[layer]));
}

// ---------------- fused tail: conv4 + conv5 + FC5 + LN + PReLU + FC6 (one block) ----------------
__global__ void __launch_bounds__(256, 1)
tail_kernel(const float* __restrict__ c3,
            const float* __restrict__ cw, const float* __restrict__ cbv,
            const float* __restrict__ bg, const float* __restrict__ bb,
            const float* __restrict__ bm, const float* __restrict__ bv,
            const float* __restrict__ pa,
            const float* __restrict__ fc5w, const float* __restrict__ fc5b,
            const float* __restrict__ lng,  const float* __restrict__ lnb,
            const float* __restrict__ p5a,
            const float* __restrict__ fc6w, const float* __restrict__ fc6b,
            float* __restrict__ out)
{
    __shared__ float c4s[2500];
    __shared__ float c5s[256];
    __shared__ float h[82];
    __shared__ float mu_s, rstd_s;
    const int t = threadIdx.x;

    // ---- conv4: g_c3 (151x151) -> c4s (50x50)
    {
        const int layer = 3;
        float w[9];
#pragma unroll
        for (int dy = 0; dy < 3; dy++)
#pragma unroll
            for (int dx = 0; dx < 3; dx++)
                w[dy * 3 + dx] = cw[layer * 9 + dx * 3 + dy];
        float rs = rsqrtf(bv[layer] + 1e-5f);
        float sc = bg[layer] * rs;
        float sh = bb[layer] - bg[layer] * bm[layer] * rs;
        for (int o = t; o < 2500; o += 256) {
            int i = o / 50, j = o % 50;
            c4s[o] = conv_point(c3, 151, i, j, w, cbv[layer], sc, sh, pa[layer]);
        }
    }
    __syncthreads();

    // ---- conv5: c4s (50x50) -> c5s (16x16)
    {
        const int layer = 4;
        float w[9];
#pragma unroll
        for (int dy = 0; dy < 3; dy++)
#pragma unroll
            for (int dx = 0; dx < 3; dx++)
                w[dy * 3 + dx] = cw[layer * 9 + dx * 3 + dy];
        float rs = rsqrtf(bv[layer] + 1e-5f);
        float sc = bg[layer] * rs;
        float sh = bb[layer] - bg[layer] * bm[layer] * rs;
        if (t < 256) {
            int i = t >> 4, j = t & 15;
            c5s[t] = conv_point(c4s, 50, i, j, w, cbv[layer], sc, sh, pa[layer]);
        }
    }
    __syncthreads();

    // ---- FC5 (un-transpose flatten: v=i*16+j reads c5s[j*16+i])
    for (int o = t; o < 82; o += 256) {
        float acc = fc5b[o];
        for (int v = 0; v < 256; v++) {
            int i = v >> 4, j = v & 15;
            acc = fmaf(c5s[j * 16 + i], fc5w[v * 82 + o], acc);
        }
        h[o] = acc;
    }
    __syncthreads();
    if (t == 0) {
        float mu = 0.0f;
        for (int o = 0; o < 82; o++) mu += h[o];
        mu *= (1.0f / 82.0f);
        float var = 0.0f;
        for (int o = 0; o < 82; o++) { float dd = h[o] - mu; var = fmaf(dd, dd, var); }
        var *= (1.0f / 82.0f);
        mu_s = mu;
        rstd_s = rsqrtf(var + 1e-5f);
    }
    __syncthreads();
    if (t < 5) {
        float alpha = p5a[0];
        float acc = fc6b[t];
        for (int k = 0; k < 82; k++) {
            float v = (h[k] - mu_s) * rstd_s * lng[k] + lnb[k];
            v = (v >= 0.0f) ? v : alpha * v;
            acc = fmaf(v, fc6w[k * 5 + t], acc);
        }
        out[t] = acc;
    }
}

// ---------------- launch ----------------
extern "C" void kernel_launch(void* const* d_in, const int* in_sizes, int n_in,
                              void* d_out, int out_size)
{
    const float* xr    = (const float*)d_in[0];
    const float* xi    = (const float*)d_in[1];
    const float* mk    = (const float*)d_in[2];
    const float* pk    = (const float*)d_in[3];
    const float* convw = (const float*)d_in[4];
    const float* convb = (const float*)d_in[5];
    const float* bng   = (const float*)d_in[6];
    const float* bnb   = (const float*)d_in[7];
    const float* bnm   = (const float*)d_in[8];
    const float* bnv   = (const float*)d_in[9];
    const float* pra   = (const float*)d_in[10];
    const float* fc5w  = (const float*)d_in[11];
    const float* fc5b  = (const float*)d_in[12];
    const float* lng   = (const float*)d_in[13];
    const float* lnb   = (const float*)d_in[14];
    const float* p5a   = (const float*)d_in[15];
    const float* fc6w  = (const float*)d_in[16];
    const float* fc6b  = (const float*)d_in[17];
    float* out = (float*)d_out;

    cudaFuncSetAttribute(fft_pass1, cudaFuncAttributeMaxDynamicSharedMemorySize, 65536);
    cudaFuncSetAttribute(fft_pass2, cudaFuncAttributeMaxDynamicSharedMemorySize, 65536);

    float *img, *c1, *c2, *c3;
    cudaGetSymbolAddress((void**)&img, g_img);
    cudaGetSymbolAddress((void**)&c1,  g_c1);
    cudaGetSymbolAddress((void**)&c2,  g_c2);
    cudaGetSymbolAddress((void**)&c3,  g_c3);

    twiddle_init<<<1, 1024>>>();
    fft_pass1<<<4096, 512, 65536>>>(xr, xi, mk, pk);
    transpose_c<<<dim3(128, 128), dim3(32, 8)>>>();
    fft_pass2<<<4096, 512, 65536>>>();

    dim3 cb(32, 8);
    conv_bn_prelu<<<dim3((1365 + 31) / 32, (1365 + 7) / 8), cb>>>(img, c1, 4096, 1365, 1365,
        convw, convb, bng, bnb, bnm, bnv, pra, 0);
    conv_bn_prelu<<<dim3((455 + 31) / 32, (455 + 7) / 8), cb>>>(c1, c2, 1365, 455, 455,
        convw, convb, bng, bnb, bnm, bnv, pra, 1);
    conv_bn_prelu<<<dim3((151 + 31) / 32, (151 + 7) / 8), cb>>>(c2, c3, 455, 151, 151,
        convw, convb, bng, bnb, bnm, bnv, pra, 2);

    tail_kernel<<<1, 256>>>(c3, convw, convb, bng, bnb, bnm, bnv, pra,
                            fc5w, fc5b, lng, lnb, p5a, fc6w, fc6b, out);
}

// round 5
// speedup vs baseline: 1.7084x; 1.1004x over previous
#include <cuda_runtime.h>
#include <math.h>

#define N 4096
#define NN (4096ULL*4096ULL)

// ---------------- scratch (device globals; no runtime allocation) ----------------
__device__ float2 g_bufA[NN];        // 128 MB: after row FFT (pass 1)
__device__ float2 g_bufB[NN];        // 128 MB: transposed
__device__ float  g_img[NN];         // 64 MB: real spatial image (TRANSPOSED orientation)
__device__ float  g_c1[1365*1365];
__device__ float  g_c2[455*455];
__device__ float  g_c3[151*151];
__device__ float2 g_tw[1024];        // W[k] = exp(+2*pi*i*k/4096)

// ---------------- complex helpers ----------------
__device__ __forceinline__ float2 cmul(float2 a, float2 b) {
    return make_float2(fmaf(a.x, b.x, -a.y * b.y), fmaf(a.x, b.y, a.y * b.x));
}
__device__ __forceinline__ float2 cadd(float2 a, float2 b) { return make_float2(a.x + b.x, a.y + b.y); }
__device__ __forceinline__ float2 csub(float2 a, float2 b) { return make_float2(a.x - b.x, a.y - b.y); }
__device__ __forceinline__ float2 cmuli(float2 z) { return make_float2(-z.y, z.x); }

// Bank-conflict-killing smem index swizzle.
__device__ __forceinline__ int SW(int i) { return i ^ ((i >> 4) & 15); }

// ---------------- fast atan2 (11th-order minimax, ~1e-7 abs err) ----------------
__device__ __forceinline__ float fast_atan2f(float y, float x)
{
    float ax = fabsf(x), ay = fabsf(y);
    float mx = fmaxf(ax, ay);
    float mn = fminf(ax, ay);
    float r  = __fdividef(mn, mx);
    float s  = r * r;
    float p  =             -0.0117212f;
    p = fmaf(p, s,  0.05265332f);
    p = fmaf(p, s, -0.11643287f);
    p = fmaf(p, s,  0.19354346f);
    p = fmaf(p, s, -0.33262347f);
    p = fmaf(p, s,  0.99997726f);
    float a = p * r;
    a = (ay > ax) ? (1.5707963267948966f - a) : a;
    a = (x < 0.0f) ? (3.1415926535897932f - a) : a;
    return (y < 0.0f) ? -a : a;
}

// ---------------- twiddle init (float, fast; replays inside the graph) ----------------
__global__ void twiddle_init() {
    int k = threadIdx.x;  // 1024 threads
    float sp, cp;
    sincospif(2.0f * (float)k / 4096.0f, &sp, &cp);
    g_tw[k] = make_float2(cp, sp);
}

// ---------------- Stockham radix-8 inverse FFT stage, IN-PLACE (compile-time S) ----------------
// reads all inputs to registers, barrier, writes outputs to the SAME buffer, barrier.
template<int S>
__device__ __forceinline__ void stage8_ip(float2* __restrict__ buf, int t)
{
    const float R8 = 0.70710678118654752f;
    const int q  = t & (S - 1);
    const int ps = t - q;

    float2 x0 = buf[SW(t)];
    float2 x1 = buf[SW(t + 512)];
    float2 x2 = buf[SW(t + 1024)];
    float2 x3 = buf[SW(t + 1536)];
    float2 x4 = buf[SW(t + 2048)];
    float2 x5 = buf[SW(t + 2560)];
    float2 x6 = buf[SW(t + 3072)];
    float2 x7 = buf[SW(t + 3584)];

    float2 apc = cadd(x0, x4), amc = csub(x0, x4);
    float2 bpd = cadd(x2, x6), bmd = csub(x2, x6);
    float2 E0 = cadd(apc, bpd);
    float2 E1 = cadd(amc, cmuli(bmd));
    float2 E2 = csub(apc, bpd);
    float2 E3 = csub(amc, cmuli(bmd));

    float2 opc = cadd(x1, x5), omc = csub(x1, x5);
    float2 ppd = cadd(x3, x7), pmd = csub(x3, x7);
    float2 O0 = cadd(opc, ppd);
    float2 O1 = cadd(omc, cmuli(pmd));
    float2 O2 = csub(opc, ppd);
    float2 O3 = csub(omc, cmuli(pmd));

    float2 T1 = cmul(make_float2( R8, R8), O1);
    float2 T2 = cmuli(O2);
    float2 T3 = cmul(make_float2(-R8, R8), O3);

    float2 y0 = cadd(E0, O0), y4 = csub(E0, O0);
    float2 y1 = cadd(E1, T1), y5 = csub(E1, T1);
    float2 y2 = cadd(E2, T2), y6 = csub(E2, T2);
    float2 y3 = cadd(E3, T3), y7 = csub(E3, T3);

    if (S != 512) {  // S==512 -> ps==0 -> all twiddles are 1
        float2 w1 = g_tw[ps];
        float2 w2 = cmul(w1, w1);
        float2 w3 = cmul(w2, w1);
        float2 w4 = cmul(w2, w2);
        float2 w5 = cmul(w3, w2);
        float2 w6 = cmul(w3, w3);
        float2 w7 = cmul(w4, w3);
        y1 = cmul(w1, y1); y2 = cmul(w2, y2); y3 = cmul(w3, y3);
        y4 = cmul(w4, y4); y5 = cmul(w5, y5); y6 = cmul(w6, y6);
        y7 = cmul(w7, y7);
    }

    __syncthreads();   // all reads done before any write

    const int ob = q + 8 * ps;
    buf[SW(ob)]         = y0;
    buf[SW(ob + S)]     = y1;
    buf[SW(ob + 2 * S)] = y2;
    buf[SW(ob + 3 * S)] = y3;
    buf[SW(ob + 4 * S)] = y4;
    buf[SW(ob + 5 * S)] = y5;
    buf[SW(ob + 6 * S)] = y6;
    buf[SW(ob + 7 * S)] = y7;

    __syncthreads();   // all writes done before next stage reads
}

__device__ __forceinline__ void fft4096_ip(float2* buf, int t)
{
    stage8_ip<1>(buf, t);
    stage8_ip<8>(buf, t);
    stage8_ip<64>(buf, t);
    stage8_ip<512>(buf, t);
}

// ---------------- pass 1: elementwise (fast math) fused + row IFFT along axis -1 ----------------
__global__ void __launch_bounds__(512, 3)
fft_pass1(const float* __restrict__ xr, const float* __restrict__ xi,
          const float* __restrict__ mk, const float* __restrict__ pk)
{
    extern __shared__ float2 sm[];
    float2* s0 = sm;
    const int row = blockIdx.x;
    const int t   = threadIdx.x;
    const int base4 = row * (N / 4);
    const float4* xr4 = (const float4*)xr;
    const float4* xi4 = (const float4*)xi;
    const float4* mk4 = (const float4*)mk;
    const float4* pk4 = (const float4*)pk;
#pragma unroll
    for (int e = 0; e < 2; e++) {
        int i4 = t + 512 * e;
        float4 ar = xr4[base4 + i4];
        float4 br = xi4[base4 + i4];
        float4 mr = mk4[base4 + i4];
        float4 pr = pk4[base4 + i4];
        float av[4] = {ar.x, ar.y, ar.z, ar.w};
        float bv[4] = {br.x, br.y, br.z, br.w};
        float mv[4] = {mr.x, mr.y, mr.z, mr.w};
        float pv[4] = {pr.x, pr.y, pr.z, pr.w};
#pragma unroll
        for (int j = 0; j < 4; j++) {
            float a = av[j], b = bv[j];
            float m = sqrtf(fmaf(a, a, b * b)) * mv[j];
            float p = fast_atan2f(b, a) * pv[j];
            float sp, cp;
            __sincosf(p, &sp, &cp);
            s0[SW(4 * i4 + j)] = make_float2(m * cp, m * sp);
        }
    }
    __syncthreads();
    fft4096_ip(s0, t);
    const int base2 = row * (N / 2);
    float4* outA = (float4*)g_bufA;
#pragma unroll
    for (int e = 0; e < 4; e++) {
        int i2 = t + 512 * e;
        float2 a = s0[SW(2 * i2)];
        float2 b = s0[SW(2 * i2 + 1)];
        outA[base2 + i2] = make_float4(a.x, a.y, b.x, b.y);
    }
}

// ---------------- complex transpose (32x32 tiles) ----------------
__global__ void __launch_bounds__(256)
transpose_c()
{
    __shared__ float2 tile[32][33];
    int x  = blockIdx.x * 32 + threadIdx.x;
    int y0 = blockIdx.y * 32;
#pragma unroll
    for (int j = threadIdx.y; j < 32; j += 8)
        tile[j][threadIdx.x] = g_bufA[(size_t)(y0 + j) * N + x];
    __syncthreads();
    int x2 = blockIdx.y * 32 + threadIdx.x;
    int y2 = blockIdx.x * 32;
#pragma unroll
    for (int j = threadIdx.y; j < 32; j += 8)
        g_bufB[(size_t)(y2 + j) * N + x2] = tile[threadIdx.x][j];
}

// ---------------- pass 2: IFFT along original axis -2, write real part ----------------
__global__ void __launch_bounds__(512, 3)
fft_pass2()
{
    extern __shared__ float2 sm[];
    float2* s0 = sm;
    const int row = blockIdx.x;        // n2
    const int t   = threadIdx.x;
    const int base2 = row * (N / 2);
    const float4* inB = (const float4*)g_bufB;
#pragma unroll
    for (int e = 0; e < 4; e++) {
        int i2 = t + 512 * e;
        float4 v = inB[base2 + i2];
        s0[SW(2 * i2)]     = make_float2(v.x, v.y);
        s0[SW(2 * i2 + 1)] = make_float2(v.z, v.w);
    }
    __syncthreads();
    fft4096_ip(s0, t);
    const float scale = 1.0f / 16777216.0f;   // 1/N^2
    const float sg0 = (row & 1) ? -scale : scale;
    const int base4 = row * (N / 4);
    float4* outI = (float4*)g_img;
#pragma unroll
    for (int e = 0; e < 2; e++) {
        int i4 = t + 512 * e;
        int idx = 4 * i4;
        float v0 = s0[SW(idx)].x     *  sg0;
        float v1 = s0[SW(idx + 1)].x * -sg0;
        float v2 = s0[SW(idx + 2)].x *  sg0;
        float v3 = s0[SW(idx + 3)].x * -sg0;
        outI[base4 + i4] = make_float4(v0, v1, v2, v3);
    }
}

// ---------------- conv 3x3 stride 3 + bias + BN + PReLU (on TRANSPOSED image) ----------------
__device__ __forceinline__ float conv_point(const float* __restrict__ in, int Win,
                                            int i, int j, const float* w,
                                            float cb, float sc, float sh, float al)
{
    const float* r0 = in + (size_t)(3 * i) * Win + 3 * j;
    float acc = 0.0f;
#pragma unroll
    for (int dy = 0; dy < 3; dy++)
#pragma unroll
        for (int dx = 0; dx < 3; dx++)
            acc = fmaf(r0[(size_t)dy * Win + dx], w[dy * 3 + dx], acc);
    acc += cb;
    acc = fmaf(acc, sc, sh);
    return (acc >= 0.0f) ? acc : al * acc;
}

__global__ void __launch_bounds__(256)
conv_bn_prelu(const float* __restrict__ in, float* __restrict__ out,
              int Win, int Wout, int Hout,
              const float* __restrict__ cw, const float* __restrict__ cb,
              const float* __restrict__ bg, const float* __restrict__ bb,
              const float* __restrict__ bm, const float* __restrict__ bv,
              const float* __restrict__ pa, int layer)
{
    int j = blockIdx.x * blockDim.x + threadIdx.x;
    int i = blockIdx.y * blockDim.y + threadIdx.y;
    if (i >= Hout || j >= Wout) return;
    const float* wb = cw + layer * 9;
    float w[9];
#pragma unroll
    for (int dy = 0; dy < 3; dy++)
#pragma unroll
        for (int dx = 0; dx < 3; dx++)
            w[dy * 3 + dx] = __ldg(&wb[dx * 3 + dy]);   // transposed weight
    float rs = rsqrtf(__ldg(&bv[layer]) + 1e-5f);
    float gg = __ldg(&bg[layer]);
    float sc = gg * rs;
    float sh = __ldg(&bb[layer]) - gg * __ldg(&bm[layer]) * rs;
    out[(size_t)i * Wout + j] =
        conv_point(in, Win, i, j, w, __ldg(&cb[layer]), sc, sh, __ldg(&pa[layer]));
}

// ---------------- fused tail: conv4 + conv5 + FC5 + LN + PReLU + FC6 (one block) ----------------
__global__ void __launch_bounds__(256, 1)
tail_kernel(const float* __restrict__ c3,
            const float* __restrict__ cw, const float* __restrict__ cbv,
            const float* __restrict__ bg, const float* __restrict__ bb,
            const float* __restrict__ bm, const float* __restrict__ bv,
            const float* __restrict__ pa,
            const float* __restrict__ fc5w, const float* __restrict__ fc5b,
            const float* __restrict__ lng,  const float* __restrict__ lnb,
            const float* __restrict__ p5a,
            const float* __restrict__ fc6w, const float* __restrict__ fc6b,
            float* __restrict__ out)
{
    __shared__ float c4s[2500];
    __shared__ float c5s[256];
    __shared__ float h[82];
    __shared__ float mu_s, rstd_s;
    const int t = threadIdx.x;

    // ---- conv4: g_c3 (151x151) -> c4s (50x50)
    {
        const int layer = 3;
        float w[9];
#pragma unroll
        for (int dy = 0; dy < 3; dy++)
#pragma unroll
            for (int dx = 0; dx < 3; dx++)
                w[dy * 3 + dx] = cw[layer * 9 + dx * 3 + dy];
        float rs = rsqrtf(bv[layer] + 1e-5f);
        float sc = bg[layer] * rs;
        float sh = bb[layer] - bg[layer] * bm[layer] * rs;
        for (int o = t; o < 2500; o += 256) {
            int i = o / 50, j = o % 50;
            c4s[o] = conv_point(c3, 151, i, j, w, cbv[layer], sc, sh, pa[layer]);
        }
    }
    __syncthreads();

    // ---- conv5: c4s (50x50) -> c5s (16x16)
    {
        const int layer = 4;
        float w[9];
#pragma unroll
        for (int dy = 0; dy < 3; dy++)
#pragma unroll
            for (int dx = 0; dx < 3; dx++)
                w[dy * 3 + dx] = cw[layer * 9 + dx * 3 + dy];
        float rs = rsqrtf(bv[layer] + 1e-5f);
        float sc = bg[layer] * rs;
        float sh = bb[layer] - bg[layer] * bm[layer] * rs;
        if (t < 256) {
            int i = t >> 4, j = t & 15;
            c5s[t] = conv_point(c4s, 50, i, j, w, cbv[layer], sc, sh, pa[layer]);
        }
    }
    __syncthreads();

    // ---- FC5 (un-transpose flatten: v=i*16+j reads c5s[j*16+i])
    for (int o = t; o < 82; o += 256) {
        float acc = fc5b[o];
        for (int v = 0; v < 256; v++) {
            int i = v >> 4, j = v & 15;
            acc = fmaf(c5s[j * 16 + i], fc5w[v * 82 + o], acc);
        }
        h[o] = acc;
    }
    __syncthreads();
    if (t == 0) {
        float mu = 0.0f;
        for (int o = 0; o < 82; o++) mu += h[o];
        mu *= (1.0f / 82.0f);
        float var = 0.0f;
        for (int o = 0; o < 82; o++) { float dd = h[o] - mu; var = fmaf(dd, dd, var); }
        var *= (1.0f / 82.0f);
        mu_s = mu;
        rstd_s = rsqrtf(var + 1e-5f);
    }
    __syncthreads();
    if (t < 5) {
        float alpha = p5a[0];
        float acc = fc6b[t];
        for (int k = 0; k < 82; k++) {
            float v = (h[k] - mu_s) * rstd_s * lng[k] + lnb[k];
            v = (v >= 0.0f) ? v : alpha * v;
            acc = fmaf(v, fc6w[k * 5 + t], acc);
        }
        out[t] = acc;
    }
}

// ---------------- launch ----------------
extern "C" void kernel_launch(void* const* d_in, const int* in_sizes, int n_in,
                              void* d_out, int out_size)
{
    const float* xr    = (const float*)d_in[0];
    const float* xi    = (const float*)d_in[1];
    const float* mk    = (const float*)d_in[2];
    const float* pk    = (const float*)d_in[3];
    const float* convw = (const float*)d_in[4];
    const float* convb = (const float*)d_in[5];
    const float* bng   = (const float*)d_in[6];
    const float* bnb   = (const float*)d_in[7];
    const float* bnm   = (const float*)d_in[8];
    const float* bnv   = (const float*)d_in[9];
    const float* pra   = (const float*)d_in[10];
    const float* fc5w  = (const float*)d_in[11];
    const float* fc5b  = (const float*)d_in[12];
    const float* lng   = (const float*)d_in[13];
    const float* lnb   = (const float*)d_in[14];
    const float* p5a   = (const float*)d_in[15];
    const float* fc6w  = (const float*)d_in[16];
    const float* fc6b  = (const float*)d_in[17];
    float* out = (float*)d_out;

    cudaFuncSetAttribute(fft_pass1, cudaFuncAttributeMaxDynamicSharedMemorySize, 32768);
    cudaFuncSetAttribute(fft_pass2, cudaFuncAttributeMaxDynamicSharedMemorySize, 32768);

    float *img, *c1, *c2, *c3;
    cudaGetSymbolAddress((void**)&img, g_img);
    cudaGetSymbolAddress((void**)&c1,  g_c1);
    cudaGetSymbolAddress((void**)&c2,  g_c2);
    cudaGetSymbolAddress((void**)&c3,  g_c3);

    twiddle_init<<<1, 1024>>>();
    fft_pass1<<<4096, 512, 32768>>>(xr, xi, mk, pk);
    transpose_c<<<dim3(128, 128), dim3(32, 8)>>>();
    fft_pass2<<<4096, 512, 32768>>>();

    dim3 cb(32, 8);
    conv_bn_prelu<<<dim3((1365 + 31) / 32, (1365 + 7) / 8), cb>>>(img, c1, 4096, 1365, 1365,
        convw, convb, bng, bnb, bnm, bnv, pra, 0);
    conv_bn_prelu<<<dim3((455 + 31) / 32, (455 + 7) / 8), cb>>>(c1, c2, 1365, 455, 455,
        convw, convb, bng, bnb, bnm, bnv, pra, 1);
    conv_bn_prelu<<<dim3((151 + 31) / 32, (151 + 7) / 8), cb>>>(c2, c3, 455, 151, 151,
        convw, convb, bng, bnb, bnm, bnv, pra, 2);

    tail_kernel<<<1, 256>>>(c3, convw, convb, bng, bnb, bnm, bnv, pra,
                            fc5w, fc5b, lng, lnb, p5a, fc6w, fc6b, out);
}